// round 6
// baseline (speedup 1.0000x reference)
#include <cuda_runtime.h>
#include <cuda_bf16.h>
#include <cstdint>

// ---------------------------------------------------------------------------
// VQ-VAE VectorQuantizer3 forward.
// R6: single-term bf16 distance GEMM (K=256) on mma.sync with fully-resident
// smem tiles (no mainloop syncs), margin-widened candidates + exact fp32
// rescore (bit-identical to R2 epilogue). Launches fused so the mma kernel is
// launch #4 (ncu capture slot).
// Out: out(8388608) | loss(1) | idx(8192)   (float32)
// ---------------------------------------------------------------------------

#define NROWS 8192
#define EDIM  256
#define NCODE 16384
#define PIN   1024
#define OUT_ELEMS 8388608
#define TKP 18
#define CAND_MARGIN 1e-3f
#define SB_OFF 67584                 // A: 128 rows * 528B
#define DSMEM (67584 + 135168)       // + B: 256 rows * 528B = 202752

typedef unsigned long long ull;

// ------------------------------ scratch -------------------------------------
__device__ float g_patches[NROWS * PIN];
__device__ float g_x[NROWS * EDIM];
__device__ float g_zf[NROWS * EDIM];
__device__ float g_rn[NROWS];
__device__ float g_wpet[EDIM * PIN];
__device__ float g_wput[PIN * EDIM];
__device__ float g_en[NCODE];
__device__ float g_outp[NROWS * PIN];
__device__ __nv_bfloat16 g_zbf[NROWS * EDIM];   // bf16(zf)
__device__ __nv_bfloat16 g_ebf[NCODE * EDIM];   // bf16(emb)
__device__ float g_cd[NROWS * 256];             // top-4 per (row, 256-code tile)
__device__ int   g_cj[NROWS * 256];
__device__ int   g_idx[NROWS];
__device__ float g_losspart[64];

// ------------------------------ fp32x2 helpers -------------------------------
__device__ __forceinline__ ull fma2(ull a, ull b, ull c) {
    ull d;
    asm("fma.rn.f32x2 %0, %1, %2, %3;" : "=l"(d) : "l"(a), "l"(b), "l"(c));
    return d;
}
__device__ __forceinline__ void unpack2(ull v, float& lo, float& hi) {
    asm("mov.b64 {%0, %1}, %2;" : "=f"(lo), "=f"(hi) : "l"(v));
}
__device__ __forceinline__ float4 ld4(const float* p) {
    return *reinterpret_cast<const float4*>(p);
}
__device__ __forceinline__ void st4(float* p, float4 v) {
    p[0] = v.x; p[1] = v.y; p[2] = v.z; p[3] = v.w;
}
__device__ __forceinline__ ull lds2(const float* p) {
    return *reinterpret_cast<const ull*>(p);
}

// ------------------------------ mma helpers ----------------------------------
__device__ __forceinline__ uint32_t smem_u32(const void* p) {
    uint32_t a;
    asm("{ .reg .u64 t; cvta.to.shared.u64 t, %1; cvt.u32.u64 %0, t; }"
        : "=r"(a) : "l"(p));
    return a;
}
__device__ __forceinline__ void cpa16(uint32_t dst, const void* src) {
    asm volatile("cp.async.ca.shared.global [%0], [%1], 16;"
                 :: "r"(dst), "l"(src) : "memory");
}
#define CP_COMMIT() asm volatile("cp.async.commit_group;" ::: "memory")
#define CP_WAIT0()  asm volatile("cp.async.wait_group 0;" ::: "memory")

__device__ __forceinline__ void ldm4(uint32_t& r0, uint32_t& r1,
                                     uint32_t& r2, uint32_t& r3, uint32_t a) {
    asm volatile("ldmatrix.sync.aligned.m8n8.x4.shared.b16 {%0,%1,%2,%3}, [%4];"
                 : "=r"(r0), "=r"(r1), "=r"(r2), "=r"(r3) : "r"(a));
}
__device__ __forceinline__ void mma_bf16(float* c, uint32_t a0, uint32_t a1,
                                         uint32_t a2, uint32_t a3,
                                         uint32_t b0, uint32_t b1) {
    asm volatile(
        "mma.sync.aligned.m16n8k16.row.col.f32.bf16.bf16.f32 "
        "{%0,%1,%2,%3}, {%4,%5,%6,%7}, {%8,%9}, {%0,%1,%2,%3};"
        : "+f"(c[0]), "+f"(c[1]), "+f"(c[2]), "+f"(c[3])
        : "r"(a0), "r"(a1), "r"(a2), "r"(a3), "r"(b0), "r"(b1));
}

// ---------------------------------------------------------------------------
// k_pre1 (launch 1): patchify + both weight transposes + emb bf16 split + norms
// blocks [0,32768): patchify; [32768,34816): transposes; [34816,51200): emb prep
// ---------------------------------------------------------------------------
__global__ void k_pre1(const float* __restrict__ z,
                       const float* __restrict__ W_pe,
                       const float* __restrict__ W_pu,
                       const float* __restrict__ emb,
                       float* __restrict__ patches,
                       float* __restrict__ wpet, float* __restrict__ wput,
                       __nv_bfloat16* __restrict__ ebf, float* __restrict__ en) {
    int b = blockIdx.x, t = threadIdx.x;
    if (b < 32768) {
        int gid = b * 256 + t;
        int kin = gid & 1023;
        int n   = gid >> 10;
        int ch = kin >> 2, ph = (kin >> 1) & 1, pw = kin & 1;
        int bi = n >> 10, li = n & 1023, hpi = li >> 5, wpi = li & 31;
        patches[gid] = z[(((size_t)(bi * 256 + ch) * 64) + hpi * 2 + ph) * 64
                         + wpi * 2 + pw];
    } else if (b < 34816) {
        int gid = (b - 32768) * 256 + t;
        if (gid < 262144) {            // wpet[e,kin] = W_pe[kin,e]
            int n = gid >> 10, k = gid & 1023;
            wpet[gid] = W_pe[k * 256 + n];
        } else {                       // wput[p,e] = W_pu[e,p]
            int g2 = gid - 262144;
            int n = g2 >> 8, k = g2 & 255;
            wput[g2] = W_pu[k * 1024 + n];
        }
    } else {
        int j = b - 34816;             // emb row
        float v = emb[(size_t)j * 256 + t];
        ebf[(size_t)j * 256 + t] = __float2bfloat16(v);
        float s = v * v;
        #pragma unroll
        for (int o = 16; o > 0; o >>= 1) s += __shfl_xor_sync(0xffffffffu, s, o);
        __shared__ float sm[8];
        if ((t & 31) == 0) sm[t >> 5] = s;
        __syncthreads();
        if (t == 0) {
            float tot = 0.0f;
            #pragma unroll
            for (int w = 0; w < 8; ++w) tot += sm[w];
            en[j] = tot;
        }
    }
}

// ---------------------------------------------------------------------------
// fp32 NT GEMM (launch 2 and 6)
// ---------------------------------------------------------------------------
template<bool GATHER>
__global__ void __launch_bounds__(256, 1)
k_gemm(const float* __restrict__ A, const float* __restrict__ B,
       const float* __restrict__ bias, float* __restrict__ C,
       const int* __restrict__ gidx, int K, int N, int kchunks) {
    __shared__ float sA[2][128 * TKP];
    __shared__ float sB[2][128 * TKP];
    int t = threadIdx.x;
    int tx = t & 15, ty = t >> 4;
    int rb = blockIdx.x * 128, cb = blockIdx.y * 128;

    int lr0 = t >> 2, q = t & 3;
    int sb0 = lr0 * TKP + q * 4;
    int sb1 = (64 + lr0) * TKP + q * 4;

    long ar0 = GATHER ? (long)gidx[rb + lr0]       : (long)(rb + lr0);
    long ar1 = GATHER ? (long)gidx[rb + 64 + lr0]  : (long)(rb + 64 + lr0);
    const float* ap0 = A + ar0 * K + q * 4;
    const float* ap1 = A + ar1 * K + q * 4;
    const float* bp0 = B + (long)(cb + lr0) * K + q * 4;
    const float* bp1 = B + (long)(cb + 64 + lr0) * K + q * 4;

    ull acc[8][8];
    #pragma unroll
    for (int i = 0; i < 8; ++i)
        #pragma unroll
        for (int j = 0; j < 8; ++j) acc[i][j] = 0ull;

    float4 ra0 = ld4(ap0), ra1 = ld4(ap1), rb0 = ld4(bp0), rb1 = ld4(bp1);
    st4(&sA[0][sb0], ra0); st4(&sA[0][sb1], ra1);
    st4(&sB[0][sb0], rb0); st4(&sB[0][sb1], rb1);
    __syncthreads();

    for (int kc = 0; kc < kchunks; ++kc) {
        if (kc + 1 < kchunks) {
            int off = (kc + 1) * 16;
            ra0 = ld4(ap0 + off); ra1 = ld4(ap1 + off);
            rb0 = ld4(bp0 + off); rb1 = ld4(bp1 + off);
        }
        const float* As = sA[kc & 1];
        const float* Bs = sB[kc & 1];
        #pragma unroll
        for (int kp = 0; kp < 8; ++kp) {
            ull a2[8], b2[8];
            #pragma unroll
            for (int i = 0; i < 8; ++i) a2[i] = lds2(As + (ty + 16 * i) * TKP + kp * 2);
            #pragma unroll
            for (int j = 0; j < 8; ++j) b2[j] = lds2(Bs + (tx + 16 * j) * TKP + kp * 2);
            #pragma unroll
            for (int i = 0; i < 8; ++i)
                #pragma unroll
                for (int j = 0; j < 8; ++j) acc[i][j] = fma2(a2[i], b2[j], acc[i][j]);
        }
        if (kc + 1 < kchunks) {
            int nb = (kc + 1) & 1;
            st4(&sA[nb][sb0], ra0); st4(&sA[nb][sb1], ra1);
            st4(&sB[nb][sb0], rb0); st4(&sB[nb][sb1], rb1);
            __syncthreads();
        }
    }

    float breg[8];
    #pragma unroll
    for (int j = 0; j < 8; ++j) breg[j] = bias[cb + tx + 16 * j];
    #pragma unroll
    for (int i = 0; i < 8; ++i) {
        long row = rb + ty + 16 * i;
        #pragma unroll
        for (int j = 0; j < 8; ++j) {
            float lo, hi; unpack2(acc[i][j], lo, hi);
            C[row * N + cb + tx + 16 * j] = lo + hi + breg[j];
        }
    }
}

// ---------------------------------------------------------------------------
// LayerNorm (launch 3) -> zf, rn = ||zf||^2, zbf = bf16(zf)
// ---------------------------------------------------------------------------
__global__ void k_ln(const float* __restrict__ x, const float* __restrict__ gamma,
                     const float* __restrict__ beta, float* __restrict__ zf,
                     float* __restrict__ rn, __nv_bfloat16* __restrict__ zbf) {
    int w = threadIdx.x >> 5, lane = threadIdx.x & 31;
    int row = blockIdx.x * 8 + w;
    const float4* xr = reinterpret_cast<const float4*>(x + (size_t)row * EDIM);
    float4 v0 = xr[lane * 2], v1 = xr[lane * 2 + 1];
    float s = v0.x+v0.y+v0.z+v0.w + v1.x+v1.y+v1.z+v1.w;
    #pragma unroll
    for (int o = 16; o > 0; o >>= 1) s += __shfl_xor_sync(0xffffffffu, s, o);
    float mu = s * (1.0f / 256.0f);
    float d0x=v0.x-mu, d0y=v0.y-mu, d0z=v0.z-mu, d0w=v0.w-mu;
    float d1x=v1.x-mu, d1y=v1.y-mu, d1z=v1.z-mu, d1w=v1.w-mu;
    float s2 = d0x*d0x+d0y*d0y+d0z*d0z+d0w*d0w + d1x*d1x+d1y*d1y+d1z*d1z+d1w*d1w;
    #pragma unroll
    for (int o = 16; o > 0; o >>= 1) s2 += __shfl_xor_sync(0xffffffffu, s2, o);
    float rs = rsqrtf(s2 * (1.0f / 256.0f) + 1e-5f);
    const float4* g4 = reinterpret_cast<const float4*>(gamma);
    const float4* b4 = reinterpret_cast<const float4*>(beta);
    float4 ga = g4[lane * 2], gb = g4[lane * 2 + 1];
    float4 ba = b4[lane * 2], bb = b4[lane * 2 + 1];
    float4 o0, o1;
    o0.x = d0x*rs*ga.x + ba.x; o0.y = d0y*rs*ga.y + ba.y;
    o0.z = d0z*rs*ga.z + ba.z; o0.w = d0w*rs*ga.w + ba.w;
    o1.x = d1x*rs*gb.x + bb.x; o1.y = d1y*rs*gb.y + bb.y;
    o1.z = d1z*rs*gb.z + bb.z; o1.w = d1w*rs*gb.w + bb.w;
    float4* zr = reinterpret_cast<float4*>(zf + (size_t)row * EDIM);
    zr[lane * 2] = o0; zr[lane * 2 + 1] = o1;
    // bf16 copy (packed 16B store)
    uint4 bfp;
    __nv_bfloat162 p0 = __float22bfloat162_rn(make_float2(o0.x, o0.y));
    __nv_bfloat162 p1 = __float22bfloat162_rn(make_float2(o0.z, o0.w));
    __nv_bfloat162 p2 = __float22bfloat162_rn(make_float2(o1.x, o1.y));
    __nv_bfloat162 p3 = __float22bfloat162_rn(make_float2(o1.z, o1.w));
    bfp.x = *reinterpret_cast<uint32_t*>(&p0);
    bfp.y = *reinterpret_cast<uint32_t*>(&p1);
    bfp.z = *reinterpret_cast<uint32_t*>(&p2);
    bfp.w = *reinterpret_cast<uint32_t*>(&p3);
    *reinterpret_cast<uint4*>(zbf + (size_t)row * EDIM + lane * 8) = bfp;
    float q2 = o0.x*o0.x+o0.y*o0.y+o0.z*o0.z+o0.w*o0.w
             + o1.x*o1.x+o1.y*o1.y+o1.z*o1.z+o1.w*o1.w;
    #pragma unroll
    for (int o = 16; o > 0; o >>= 1) q2 += __shfl_xor_sync(0xffffffffu, q2, o);
    if (lane == 0) rn[row] = q2;
}

// ---------------------------------------------------------------------------
// mma.sync distance kernel (launch 4). CTA: 128 rows x 256 codes, K=256.
// A and B fully resident in smem -> zero mainloop syncs.
// 256 threads = 8 warps (2 row x 4 col), warp tile 64x64.
// Epilogue: top-4 smallest d_a = en[j] - 2*dot per (row, 256-tile).
// ---------------------------------------------------------------------------
__global__ void __launch_bounds__(256, 1)
k_mma_dist(const __nv_bfloat16* __restrict__ zbf,
           const __nv_bfloat16* __restrict__ ebf,
           const float* __restrict__ en,
           float* __restrict__ cd, int* __restrict__ cj) {
    extern __shared__ char smem[];
    uint32_t sb = smem_u32(smem);
    int t = threadIdx.x, lane = t & 31, w = t >> 5;
    int wr = w >> 2, wc = w & 3;
    int g = lane >> 2, tid4 = lane & 3;
    int rb = blockIdx.x * 128, jb = blockIdx.y * 256;

    // prologue: A rows (row = t>>1, half = t&1), B rows (row = t)
    {
        int row = t >> 1, half = t & 1;
        const char* ga = (const char*)(zbf + (size_t)(rb + row) * EDIM) + half * 256;
        uint32_t da = sb + (uint32_t)row * 528 + half * 256;
        #pragma unroll
        for (int c2 = 0; c2 < 16; ++c2) cpa16(da + c2 * 16, ga + c2 * 16);
        const char* gb = (const char*)(ebf + (size_t)(jb + t) * EDIM);
        uint32_t db = sb + SB_OFF + (uint32_t)t * 528;
        #pragma unroll
        for (int c2 = 0; c2 < 32; ++c2) cpa16(db + c2 * 16, gb + c2 * 16);
    }
    CP_COMMIT();
    CP_WAIT0();
    __syncthreads();

    float c[4][8][4];
    #pragma unroll
    for (int mi = 0; mi < 4; ++mi)
        #pragma unroll
        for (int ni = 0; ni < 8; ++ni)
            #pragma unroll
            for (int s = 0; s < 4; ++s) c[mi][ni][s] = 0.0f;

    uint32_t ab_base = sb + (uint32_t)(wr * 64 + (lane & 15)) * 528 + (lane >> 4) * 16;
    uint32_t bb_base = sb + SB_OFF
                     + (uint32_t)(wc * 64 + (lane & 7) + ((lane >> 4) & 1) * 8) * 528
                     + ((lane >> 3) & 1) * 16;

    #pragma unroll
    for (int kc = 0; kc < 8; ++kc) {
        uint32_t koff = (uint32_t)kc * 64;
        #pragma unroll
        for (int kh = 0; kh < 2; ++kh) {
            uint32_t A0[4], A1[4], A2[4], A3[4];
            #pragma unroll
            for (int mi = 0; mi < 4; ++mi)
                ldm4(A0[mi], A1[mi], A2[mi], A3[mi],
                     ab_base + mi * (16 * 528) + koff + kh * 32);
            uint32_t B0[4], B1[4], B2[4], B3[4];
            #pragma unroll
            for (int np = 0; np < 4; ++np)
                ldm4(B0[np], B1[np], B2[np], B3[np],
                     bb_base + np * (16 * 528) + koff + kh * 32);
            #pragma unroll
            for (int mi = 0; mi < 4; ++mi)
                #pragma unroll
                for (int ni = 0; ni < 8; ++ni) {
                    int np = ni >> 1;
                    if (ni & 1)
                        mma_bf16(c[mi][ni], A0[mi], A1[mi], A2[mi], A3[mi],
                                 B2[np], B3[np]);
                    else
                        mma_bf16(c[mi][ni], A0[mi], A1[mi], A2[mi], A3[mi],
                                 B0[np], B1[np]);
                }
        }
    }

    // ------------------- epilogue: top-4 per (row, tile) ---------------------
    float* md = reinterpret_cast<float*>(smem);          // [128][16]
    int*   mj = reinterpret_cast<int*>(smem + 8192);
    float enr[8][2];
    #pragma unroll
    for (int ni = 0; ni < 8; ++ni) {
        int cl = wc * 64 + ni * 8 + tid4 * 2;
        enr[ni][0] = en[jb + cl];
        enr[ni][1] = en[jb + cl + 1];
    }
    __syncthreads();   // done reading A/B smem; safe to overwrite with md/mj
    #pragma unroll
    for (int mi = 0; mi < 4; ++mi) {
        #pragma unroll
        for (int s2 = 0; s2 < 2; ++s2) {
            int row = wr * 64 + mi * 16 + g + 8 * s2;
            float bv[4] = {3.4e38f, 3.4e38f, 3.4e38f, 3.4e38f};
            int bj4[4] = {0, 0, 0, 0};
            float wmax = 3.4e38f; int wpos = 0;
            #pragma unroll
            for (int ni = 0; ni < 8; ++ni)
                #pragma unroll
                for (int p = 0; p < 2; ++p) {
                    float d = __fmaf_rn(-2.0f, c[mi][ni][s2 * 2 + p], enr[ni][p]);
                    if (d < wmax) {
                        bv[wpos] = d;
                        bj4[wpos] = jb + wc * 64 + ni * 8 + tid4 * 2 + p;
                        wmax = bv[0]; wpos = 0;
                        #pragma unroll
                        for (int s = 1; s < 4; ++s)
                            if (bv[s] > wmax) { wmax = bv[s]; wpos = s; }
                    }
                }
            #pragma unroll
            for (int off = 1; off <= 2; off <<= 1) {
                #pragma unroll
                for (int s = 0; s < 4; ++s) {
                    float od = __shfl_xor_sync(0xffffffffu, bv[s], off);
                    int   oj = __shfl_xor_sync(0xffffffffu, bj4[s], off);
                    if (od < wmax) {
                        bv[wpos] = od; bj4[wpos] = oj;
                        wmax = bv[0]; wpos = 0;
                        #pragma unroll
                        for (int q = 1; q < 4; ++q)
                            if (bv[q] > wmax) { wmax = bv[q]; wpos = q; }
                    }
                }
            }
            if (tid4 == 0) {
                #pragma unroll
                for (int s = 0; s < 4; ++s) {
                    md[row * 16 + wc * 4 + s] = bv[s];
                    mj[row * 16 + wc * 4 + s] = bj4[s];
                }
            }
        }
    }
    __syncthreads();
    if (t < 128) {
        float bv[4]; int bj4[4];
        #pragma unroll
        for (int s = 0; s < 4; ++s) { bv[s] = md[t * 16 + s]; bj4[s] = mj[t * 16 + s]; }
        float wmax = bv[0]; int wpos = 0;
        #pragma unroll
        for (int s = 1; s < 4; ++s) if (bv[s] > wmax) { wmax = bv[s]; wpos = s; }
        #pragma unroll
        for (int u = 4; u < 16; ++u) {
            float od = md[t * 16 + u]; int oj = mj[t * 16 + u];
            if (od < wmax) {
                bv[wpos] = od; bj4[wpos] = oj;
                wmax = bv[0]; wpos = 0;
                #pragma unroll
                for (int q = 1; q < 4; ++q)
                    if (bv[q] > wmax) { wmax = bv[q]; wpos = q; }
            }
        }
        size_t base = (size_t)(rb + t) * 256 + (size_t)blockIdx.y * 4;
        #pragma unroll
        for (int s = 0; s < 4; ++s) { cd[base + s] = bv[s]; cj[base + s] = bj4[s]; }
    }
}

// ---------------------------------------------------------------------------
// candidate merge + exact fp32 rescore (launch 5; R2-identical semantics)
// ---------------------------------------------------------------------------
__global__ void __launch_bounds__(256)
k_cand(const float* __restrict__ cd, const int* __restrict__ cj,
       const float* __restrict__ zf, const float* __restrict__ emb,
       const float* __restrict__ en, const float* __restrict__ rn,
       int* __restrict__ idxo, float* __restrict__ fout) {
    __shared__ int lst[8][256];
    __shared__ int cnt[8];
    int w = threadIdx.x >> 5, lane = threadIdx.x & 31;
    int row = blockIdx.x * 8 + w;
    if (lane == 0) cnt[w] = 0;
    __syncwarp();

    float dv[8]; int jv[8];
    size_t base = (size_t)row * 256 + lane * 8;
    #pragma unroll
    for (int s = 0; s < 8; ++s) { dv[s] = cd[base + s]; jv[s] = cj[base + s]; }
    float mn = dv[0];
    #pragma unroll
    for (int s = 1; s < 8; ++s) mn = fminf(mn, dv[s]);
    #pragma unroll
    for (int o = 16; o > 0; o >>= 1)
        mn = fminf(mn, __shfl_xor_sync(0xffffffffu, mn, o));
    float thr = mn + CAND_MARGIN;
    #pragma unroll
    for (int s = 0; s < 8; ++s) {
        if (dv[s] <= thr) {
            int pos = atomicAdd(&cnt[w], 1);
            lst[w][pos] = jv[s];
        }
    }
    __syncwarp();
    int m = cnt[w];

    float bd = 3.4e38f; int bj = 0x7fffffff;
    const float2* z2 = reinterpret_cast<const float2*>(zf + (size_t)row * EDIM);
    float rnv = rn[row];
    for (int cc = lane; cc < m; cc += 32) {
        int j = lst[w][cc];
        const float2* e2 = reinterpret_cast<const float2*>(emb + (size_t)j * EDIM);
        float lo = 0.0f, hi = 0.0f;
        #pragma unroll 8
        for (int q = 0; q < 128; ++q) {
            float2 zz = z2[q], ee = e2[q];
            lo = __fmaf_rn(zz.x, ee.x, lo);
            hi = __fmaf_rn(zz.y, ee.y, hi);
        }
        float dot = __fadd_rn(lo, hi);
        float t1  = __fadd_rn(rnv, en[j]);
        float d   = __fsub_rn(t1, __fmul_rn(2.0f, dot));
        if (d < bd || (d == bd && j < bj)) { bd = d; bj = j; }
    }
    #pragma unroll
    for (int o = 16; o > 0; o >>= 1) {
        float od = __shfl_xor_sync(0xffffffffu, bd, o);
        int   oj = __shfl_xor_sync(0xffffffffu, bj, o);
        if (od < bd || (od == bd && oj < bj)) { bd = od; bj = oj; }
    }
    if (lane == 0) {
        idxo[row] = bj;
        fout[OUT_ELEMS + 1 + row] = (float)bj;
    }
}

// ---------------------------------------------------------------------------
__global__ void k_loss(const float* __restrict__ zf, const float* __restrict__ emb,
                       const int* __restrict__ idx, float* __restrict__ part) {
    int t = threadIdx.x;
    size_t base = (size_t)blockIdx.x * 32768;
    float acc = 0.0f;
    for (int i = 0; i < 128; ++i) {
        size_t e = base + t + (size_t)i * 256;
        int n = (int)(e >> 8);
        float d = emb[(size_t)idx[n] * EDIM + t] - zf[e];
        acc += d * d;
    }
    __shared__ float sm[256];
    sm[t] = acc;
    __syncthreads();
    #pragma unroll
    for (int o = 128; o > 0; o >>= 1) {
        if (t < o) sm[t] += sm[t + o];
        __syncthreads();
    }
    if (t == 0) part[blockIdx.x] = sm[0];
}

__global__ void k_fin(const float* __restrict__ part, float* __restrict__ out) {
    if (threadIdx.x == 0 && blockIdx.x == 0) {
        float s = 0.0f;
        for (int i = 0; i < 64; ++i) s += part[i];
        out[OUT_ELEMS] = 1.25f * s / 2097152.0f;
    }
}

__global__ void k_unpatch(const float* __restrict__ outp, float* __restrict__ out) {
    int gid = blockIdx.x * 256 + threadIdx.x;
    int ww = gid & 63, hh = (gid >> 6) & 63;
    int ch = (gid >> 12) & 255, bi = gid >> 20;
    int n = bi * 1024 + (hh >> 1) * 32 + (ww >> 1);
    int kin = ch * 4 + (hh & 1) * 2 + (ww & 1);
    out[gid] = outp[(size_t)n * PIN + kin];
}

// ---------------------------------------------------------------------------
extern "C" void kernel_launch(void* const* d_in, const int* in_sizes, int n_in,
                              void* d_out, int out_size) {
    const float* z     = (const float*)d_in[0];
    const float* emb   = (const float*)d_in[1];
    const float* W_pe  = (const float*)d_in[2];
    const float* b_pe  = (const float*)d_in[3];
    const float* gamma = (const float*)d_in[4];
    const float* beta  = (const float*)d_in[5];
    const float* W_pu  = (const float*)d_in[6];
    const float* b_pu  = (const float*)d_in[7];
    float* out = (float*)d_out;

    float *patches, *x, *zf, *rn, *wpet, *wput, *en, *outp, *cdp, *lpart;
    __nv_bfloat16 *zbf, *ebf;
    int *cjp, *idx;
    cudaGetSymbolAddress((void**)&patches, g_patches);
    cudaGetSymbolAddress((void**)&x,       g_x);
    cudaGetSymbolAddress((void**)&zf,      g_zf);
    cudaGetSymbolAddress((void**)&rn,      g_rn);
    cudaGetSymbolAddress((void**)&wpet,    g_wpet);
    cudaGetSymbolAddress((void**)&wput,    g_wput);
    cudaGetSymbolAddress((void**)&en,      g_en);
    cudaGetSymbolAddress((void**)&outp,    g_outp);
    cudaGetSymbolAddress((void**)&zbf,     g_zbf);
    cudaGetSymbolAddress((void**)&ebf,     g_ebf);
    cudaGetSymbolAddress((void**)&cdp,     g_cd);
    cudaGetSymbolAddress((void**)&cjp,     g_cj);
    cudaGetSymbolAddress((void**)&idx,     g_idx);
    cudaGetSymbolAddress((void**)&lpart,   g_losspart);

    cudaFuncSetAttribute(k_mma_dist, cudaFuncAttributeMaxDynamicSharedMemorySize,
                         DSMEM);

    // launch 1: fused prep
    k_pre1<<<51200, 256>>>(z, W_pe, W_pu, emb, patches, wpet, wput, ebf, en);
    // launch 2: x = patches @ W_pe + b_pe
    k_gemm<false><<<dim3(64, 2), 256>>>(patches, wpet, b_pe, x, nullptr,
                                        PIN, EDIM, PIN / 16);
    // launch 3: LayerNorm (+ rn, zbf)
    k_ln<<<NROWS / 8, 256>>>(x, gamma, beta, zf, rn, zbf);
    // launch 4: tensor-core distance (profiled slot)
    k_mma_dist<<<dim3(64, 64), 256, DSMEM>>>(zbf, ebf, en, cdp, cjp);
    // launch 5: candidates + exact rescore
    k_cand<<<1024, 256>>>(cdp, cjp, zf, emb, en, rn, idx, out);
    // launch 6: outp = emb[idx] @ W_pu + b_pu
    k_gemm<true><<<dim3(64, 8), 256>>>(emb, wput, b_pu, outp, idx,
                                       EDIM, PIN, EDIM / 16);
    k_loss<<<64, 256>>>(zf, emb, idx, lpart);
    k_fin<<<1, 32>>>(lpart, out);
    k_unpatch<<<32768, 256>>>(outp, out);
    (void)in_sizes; (void)n_in; (void)out_size;
}

// round 7
// speedup vs baseline: 1.0062x; 1.0062x over previous
#include <cuda_runtime.h>
#include <cuda_bf16.h>
#include <cstdint>

// ---------------------------------------------------------------------------
// VQ-VAE VectorQuantizer3 forward.
// R7: distance kernel rebuilt for register pressure / occupancy:
//   512 threads (16 warps), warp tile 32x64 -> 64 accumulators/thread (was 128
//   @ 255 regs, spilled). Same resident-smem K=256 bf16 mma.sync design, same
//   top-4 candidates + exact fp32 rescore (bit-identical idx to R2).
// Out: out(8388608) | loss(1) | idx(8192)   (float32)
// ---------------------------------------------------------------------------

#define NROWS 8192
#define EDIM  256
#define NCODE 16384
#define PIN   1024
#define OUT_ELEMS 8388608
#define TKP 18
#define CAND_MARGIN 1e-3f
#define SB_OFF 67584                 // A: 128 rows * 528B
#define DSMEM (67584 + 135168)       // + B: 256 rows * 528B = 202752

typedef unsigned long long ull;

// ------------------------------ scratch -------------------------------------
__device__ float g_patches[NROWS * PIN];
__device__ float g_x[NROWS * EDIM];
__device__ float g_zf[NROWS * EDIM];
__device__ float g_rn[NROWS];
__device__ float g_wpet[EDIM * PIN];
__device__ float g_wput[PIN * EDIM];
__device__ float g_en[NCODE];
__device__ float g_outp[NROWS * PIN];
__device__ __nv_bfloat16 g_zbf[NROWS * EDIM];   // bf16(zf)
__device__ __nv_bfloat16 g_ebf[NCODE * EDIM];   // bf16(emb)
__device__ float g_cd[NROWS * 256];             // top-4 per (row, 256-code tile)
__device__ int   g_cj[NROWS * 256];
__device__ int   g_idx[NROWS];
__device__ float g_losspart[64];

// ------------------------------ fp32x2 helpers -------------------------------
__device__ __forceinline__ ull fma2(ull a, ull b, ull c) {
    ull d;
    asm("fma.rn.f32x2 %0, %1, %2, %3;" : "=l"(d) : "l"(a), "l"(b), "l"(c));
    return d;
}
__device__ __forceinline__ void unpack2(ull v, float& lo, float& hi) {
    asm("mov.b64 {%0, %1}, %2;" : "=f"(lo), "=f"(hi) : "l"(v));
}
__device__ __forceinline__ float4 ld4(const float* p) {
    return *reinterpret_cast<const float4*>(p);
}
__device__ __forceinline__ void st4(float* p, float4 v) {
    p[0] = v.x; p[1] = v.y; p[2] = v.z; p[3] = v.w;
}
__device__ __forceinline__ ull lds2(const float* p) {
    return *reinterpret_cast<const ull*>(p);
}

// ------------------------------ mma helpers ----------------------------------
__device__ __forceinline__ uint32_t smem_u32(const void* p) {
    uint32_t a;
    asm("{ .reg .u64 t; cvta.to.shared.u64 t, %1; cvt.u32.u64 %0, t; }"
        : "=r"(a) : "l"(p));
    return a;
}
__device__ __forceinline__ void cpa16(uint32_t dst, const void* src) {
    asm volatile("cp.async.ca.shared.global [%0], [%1], 16;"
                 :: "r"(dst), "l"(src) : "memory");
}
#define CP_COMMIT() asm volatile("cp.async.commit_group;" ::: "memory")
#define CP_WAIT0()  asm volatile("cp.async.wait_group 0;" ::: "memory")

__device__ __forceinline__ void ldm4(uint32_t& r0, uint32_t& r1,
                                     uint32_t& r2, uint32_t& r3, uint32_t a) {
    asm volatile("ldmatrix.sync.aligned.m8n8.x4.shared.b16 {%0,%1,%2,%3}, [%4];"
                 : "=r"(r0), "=r"(r1), "=r"(r2), "=r"(r3) : "r"(a));
}
__device__ __forceinline__ void mma_bf16(float* c, uint32_t a0, uint32_t a1,
                                         uint32_t a2, uint32_t a3,
                                         uint32_t b0, uint32_t b1) {
    asm volatile(
        "mma.sync.aligned.m16n8k16.row.col.f32.bf16.bf16.f32 "
        "{%0,%1,%2,%3}, {%4,%5,%6,%7}, {%8,%9}, {%0,%1,%2,%3};"
        : "+f"(c[0]), "+f"(c[1]), "+f"(c[2]), "+f"(c[3])
        : "r"(a0), "r"(a1), "r"(a2), "r"(a3), "r"(b0), "r"(b1));
}

// ---------------------------------------------------------------------------
// k_pre1 (launch 1): patchify + both weight transposes + emb bf16 + norms
// ---------------------------------------------------------------------------
__global__ void k_pre1(const float* __restrict__ z,
                       const float* __restrict__ W_pe,
                       const float* __restrict__ W_pu,
                       const float* __restrict__ emb,
                       float* __restrict__ patches,
                       float* __restrict__ wpet, float* __restrict__ wput,
                       __nv_bfloat16* __restrict__ ebf, float* __restrict__ en) {
    int b = blockIdx.x, t = threadIdx.x;
    if (b < 32768) {
        int gid = b * 256 + t;
        int kin = gid & 1023;
        int n   = gid >> 10;
        int ch = kin >> 2, ph = (kin >> 1) & 1, pw = kin & 1;
        int bi = n >> 10, li = n & 1023, hpi = li >> 5, wpi = li & 31;
        patches[gid] = z[(((size_t)(bi * 256 + ch) * 64) + hpi * 2 + ph) * 64
                         + wpi * 2 + pw];
    } else if (b < 34816) {
        int gid = (b - 32768) * 256 + t;
        if (gid < 262144) {            // wpet[e,kin] = W_pe[kin,e]
            int n = gid >> 10, k = gid & 1023;
            wpet[gid] = W_pe[k * 256 + n];
        } else {                       // wput[p,e] = W_pu[e,p]
            int g2 = gid - 262144;
            int n = g2 >> 8, k = g2 & 255;
            wput[g2] = W_pu[k * 1024 + n];
        }
    } else {
        int j = b - 34816;             // emb row
        float v = emb[(size_t)j * 256 + t];
        ebf[(size_t)j * 256 + t] = __float2bfloat16(v);
        float s = v * v;
        #pragma unroll
        for (int o = 16; o > 0; o >>= 1) s += __shfl_xor_sync(0xffffffffu, s, o);
        __shared__ float sm[8];
        if ((t & 31) == 0) sm[t >> 5] = s;
        __syncthreads();
        if (t == 0) {
            float tot = 0.0f;
            #pragma unroll
            for (int w = 0; w < 8; ++w) tot += sm[w];
            en[j] = tot;
        }
    }
}

// ---------------------------------------------------------------------------
// fp32 NT GEMM (launch 2 and 6)
// ---------------------------------------------------------------------------
template<bool GATHER>
__global__ void __launch_bounds__(256, 1)
k_gemm(const float* __restrict__ A, const float* __restrict__ B,
       const float* __restrict__ bias, float* __restrict__ C,
       const int* __restrict__ gidx, int K, int N, int kchunks) {
    __shared__ float sA[2][128 * TKP];
    __shared__ float sB[2][128 * TKP];
    int t = threadIdx.x;
    int tx = t & 15, ty = t >> 4;
    int rb = blockIdx.x * 128, cb = blockIdx.y * 128;

    int lr0 = t >> 2, q = t & 3;
    int sb0 = lr0 * TKP + q * 4;
    int sb1 = (64 + lr0) * TKP + q * 4;

    long ar0 = GATHER ? (long)gidx[rb + lr0]       : (long)(rb + lr0);
    long ar1 = GATHER ? (long)gidx[rb + 64 + lr0]  : (long)(rb + 64 + lr0);
    const float* ap0 = A + ar0 * K + q * 4;
    const float* ap1 = A + ar1 * K + q * 4;
    const float* bp0 = B + (long)(cb + lr0) * K + q * 4;
    const float* bp1 = B + (long)(cb + 64 + lr0) * K + q * 4;

    ull acc[8][8];
    #pragma unroll
    for (int i = 0; i < 8; ++i)
        #pragma unroll
        for (int j = 0; j < 8; ++j) acc[i][j] = 0ull;

    float4 ra0 = ld4(ap0), ra1 = ld4(ap1), rb0 = ld4(bp0), rb1 = ld4(bp1);
    st4(&sA[0][sb0], ra0); st4(&sA[0][sb1], ra1);
    st4(&sB[0][sb0], rb0); st4(&sB[0][sb1], rb1);
    __syncthreads();

    for (int kc = 0; kc < kchunks; ++kc) {
        if (kc + 1 < kchunks) {
            int off = (kc + 1) * 16;
            ra0 = ld4(ap0 + off); ra1 = ld4(ap1 + off);
            rb0 = ld4(bp0 + off); rb1 = ld4(bp1 + off);
        }
        const float* As = sA[kc & 1];
        const float* Bs = sB[kc & 1];
        #pragma unroll
        for (int kp = 0; kp < 8; ++kp) {
            ull a2[8], b2[8];
            #pragma unroll
            for (int i = 0; i < 8; ++i) a2[i] = lds2(As + (ty + 16 * i) * TKP + kp * 2);
            #pragma unroll
            for (int j = 0; j < 8; ++j) b2[j] = lds2(Bs + (tx + 16 * j) * TKP + kp * 2);
            #pragma unroll
            for (int i = 0; i < 8; ++i)
                #pragma unroll
                for (int j = 0; j < 8; ++j) acc[i][j] = fma2(a2[i], b2[j], acc[i][j]);
        }
        if (kc + 1 < kchunks) {
            int nb = (kc + 1) & 1;
            st4(&sA[nb][sb0], ra0); st4(&sA[nb][sb1], ra1);
            st4(&sB[nb][sb0], rb0); st4(&sB[nb][sb1], rb1);
            __syncthreads();
        }
    }

    float breg[8];
    #pragma unroll
    for (int j = 0; j < 8; ++j) breg[j] = bias[cb + tx + 16 * j];
    #pragma unroll
    for (int i = 0; i < 8; ++i) {
        long row = rb + ty + 16 * i;
        #pragma unroll
        for (int j = 0; j < 8; ++j) {
            float lo, hi; unpack2(acc[i][j], lo, hi);
            C[row * N + cb + tx + 16 * j] = lo + hi + breg[j];
        }
    }
}

// ---------------------------------------------------------------------------
// LayerNorm (launch 3) -> zf, rn = ||zf||^2, zbf = bf16(zf)
// ---------------------------------------------------------------------------
__global__ void k_ln(const float* __restrict__ x, const float* __restrict__ gamma,
                     const float* __restrict__ beta, float* __restrict__ zf,
                     float* __restrict__ rn, __nv_bfloat16* __restrict__ zbf) {
    int w = threadIdx.x >> 5, lane = threadIdx.x & 31;
    int row = blockIdx.x * 8 + w;
    const float4* xr = reinterpret_cast<const float4*>(x + (size_t)row * EDIM);
    float4 v0 = xr[lane * 2], v1 = xr[lane * 2 + 1];
    float s = v0.x+v0.y+v0.z+v0.w + v1.x+v1.y+v1.z+v1.w;
    #pragma unroll
    for (int o = 16; o > 0; o >>= 1) s += __shfl_xor_sync(0xffffffffu, s, o);
    float mu = s * (1.0f / 256.0f);
    float d0x=v0.x-mu, d0y=v0.y-mu, d0z=v0.z-mu, d0w=v0.w-mu;
    float d1x=v1.x-mu, d1y=v1.y-mu, d1z=v1.z-mu, d1w=v1.w-mu;
    float s2 = d0x*d0x+d0y*d0y+d0z*d0z+d0w*d0w + d1x*d1x+d1y*d1y+d1z*d1z+d1w*d1w;
    #pragma unroll
    for (int o = 16; o > 0; o >>= 1) s2 += __shfl_xor_sync(0xffffffffu, s2, o);
    float rs = rsqrtf(s2 * (1.0f / 256.0f) + 1e-5f);
    const float4* g4 = reinterpret_cast<const float4*>(gamma);
    const float4* b4 = reinterpret_cast<const float4*>(beta);
    float4 ga = g4[lane * 2], gb = g4[lane * 2 + 1];
    float4 ba = b4[lane * 2], bb = b4[lane * 2 + 1];
    float4 o0, o1;
    o0.x = d0x*rs*ga.x + ba.x; o0.y = d0y*rs*ga.y + ba.y;
    o0.z = d0z*rs*ga.z + ba.z; o0.w = d0w*rs*ga.w + ba.w;
    o1.x = d1x*rs*gb.x + bb.x; o1.y = d1y*rs*gb.y + bb.y;
    o1.z = d1z*rs*gb.z + bb.z; o1.w = d1w*rs*gb.w + bb.w;
    float4* zr = reinterpret_cast<float4*>(zf + (size_t)row * EDIM);
    zr[lane * 2] = o0; zr[lane * 2 + 1] = o1;
    uint4 bfp;
    __nv_bfloat162 p0 = __float22bfloat162_rn(make_float2(o0.x, o0.y));
    __nv_bfloat162 p1 = __float22bfloat162_rn(make_float2(o0.z, o0.w));
    __nv_bfloat162 p2 = __float22bfloat162_rn(make_float2(o1.x, o1.y));
    __nv_bfloat162 p3 = __float22bfloat162_rn(make_float2(o1.z, o1.w));
    bfp.x = *reinterpret_cast<uint32_t*>(&p0);
    bfp.y = *reinterpret_cast<uint32_t*>(&p1);
    bfp.z = *reinterpret_cast<uint32_t*>(&p2);
    bfp.w = *reinterpret_cast<uint32_t*>(&p3);
    *reinterpret_cast<uint4*>(zbf + (size_t)row * EDIM + lane * 8) = bfp;
    float q2 = o0.x*o0.x+o0.y*o0.y+o0.z*o0.z+o0.w*o0.w
             + o1.x*o1.x+o1.y*o1.y+o1.z*o1.z+o1.w*o1.w;
    #pragma unroll
    for (int o = 16; o > 0; o >>= 1) q2 += __shfl_xor_sync(0xffffffffu, q2, o);
    if (lane == 0) rn[row] = q2;
}

// ---------------------------------------------------------------------------
// mma.sync distance kernel (launch 4). CTA: 128 rows x 256 codes, K=256.
// 512 threads = 16 warps (4 row x 4 col), warp tile 32x64 -> 64 acc/thread.
// A and B fully resident in smem, no mainloop syncs.
// Epilogue: top-4 smallest d_a = en[j] - 2*dot per (row, 256-tile).
// ---------------------------------------------------------------------------
__global__ void __launch_bounds__(512, 1)
k_mma_dist(const __nv_bfloat16* __restrict__ zbf,
           const __nv_bfloat16* __restrict__ ebf,
           const float* __restrict__ en,
           float* __restrict__ cd, int* __restrict__ cj) {
    extern __shared__ char smem[];
    uint32_t sb = smem_u32(smem);
    int t = threadIdx.x, lane = t & 31, w = t >> 5;
    int wr = w >> 2, wc = w & 3;                 // 4x4 warp grid
    int g = lane >> 2, tid4 = lane & 3;
    int rb = blockIdx.x * 128, jb = blockIdx.y * 256;

    // prologue: A (128 rows x 512B): row = t>>2, quarter = t&3 (128B each)
    //           B (256 rows x 512B): row = t>>1, half = t&1 (256B each)
    {
        int ar = t >> 2, aq = t & 3;
        const char* ga = (const char*)(zbf + (size_t)(rb + ar) * EDIM) + aq * 128;
        uint32_t da = sb + (uint32_t)ar * 528 + aq * 128;
        #pragma unroll
        for (int c2 = 0; c2 < 8; ++c2) cpa16(da + c2 * 16, ga + c2 * 16);
        int br = t >> 1, bh = t & 1;
        const char* gb = (const char*)(ebf + (size_t)(jb + br) * EDIM) + bh * 256;
        uint32_t db = sb + SB_OFF + (uint32_t)br * 528 + bh * 256;
        #pragma unroll
        for (int c2 = 0; c2 < 16; ++c2) cpa16(db + c2 * 16, gb + c2 * 16);
    }
    CP_COMMIT();
    CP_WAIT0();
    __syncthreads();

    float c[2][8][4];
    #pragma unroll
    for (int mi = 0; mi < 2; ++mi)
        #pragma unroll
        for (int ni = 0; ni < 8; ++ni)
            #pragma unroll
            for (int s = 0; s < 4; ++s) c[mi][ni][s] = 0.0f;

    uint32_t ab_base = sb + (uint32_t)(wr * 32 + (lane & 15)) * 528 + (lane >> 4) * 16;
    uint32_t bb_base = sb + SB_OFF
                     + (uint32_t)(wc * 64 + (lane & 7) + ((lane >> 4) & 1) * 8) * 528
                     + ((lane >> 3) & 1) * 16;

    #pragma unroll 2
    for (int kc = 0; kc < 8; ++kc) {
        uint32_t koff = (uint32_t)kc * 64;
        #pragma unroll
        for (int kh = 0; kh < 2; ++kh) {
            uint32_t A0[2], A1[2], A2[2], A3[2];
            #pragma unroll
            for (int mi = 0; mi < 2; ++mi)
                ldm4(A0[mi], A1[mi], A2[mi], A3[mi],
                     ab_base + mi * (16 * 528) + koff + kh * 32);
            uint32_t B0[4], B1[4], B2[4], B3[4];
            #pragma unroll
            for (int np = 0; np < 4; ++np)
                ldm4(B0[np], B1[np], B2[np], B3[np],
                     bb_base + np * (16 * 528) + koff + kh * 32);
            #pragma unroll
            for (int mi = 0; mi < 2; ++mi)
                #pragma unroll
                for (int ni = 0; ni < 8; ++ni) {
                    int np = ni >> 1;
                    if (ni & 1)
                        mma_bf16(c[mi][ni], A0[mi], A1[mi], A2[mi], A3[mi],
                                 B2[np], B3[np]);
                    else
                        mma_bf16(c[mi][ni], A0[mi], A1[mi], A2[mi], A3[mi],
                                 B0[np], B1[np]);
                }
        }
    }

    // ------------------- epilogue: top-4 per (row, tile) ---------------------
    float* md = reinterpret_cast<float*>(smem);          // [128][16]
    int*   mj = reinterpret_cast<int*>(smem + 8192);
    float enr[8][2];
    #pragma unroll
    for (int ni = 0; ni < 8; ++ni) {
        int cl = wc * 64 + ni * 8 + tid4 * 2;
        enr[ni][0] = en[jb + cl];
        enr[ni][1] = en[jb + cl + 1];
    }
    __syncthreads();   // done reading A/B smem; safe to overwrite with md/mj
    #pragma unroll
    for (int mi = 0; mi < 2; ++mi) {
        #pragma unroll
        for (int s2 = 0; s2 < 2; ++s2) {
            int row = wr * 32 + mi * 16 + g + 8 * s2;
            float bv[4] = {3.4e38f, 3.4e38f, 3.4e38f, 3.4e38f};
            int bj4[4] = {0, 0, 0, 0};
            float wmax = 3.4e38f; int wpos = 0;
            #pragma unroll
            for (int ni = 0; ni < 8; ++ni)
                #pragma unroll
                for (int p = 0; p < 2; ++p) {
                    float d = __fmaf_rn(-2.0f, c[mi][ni][s2 * 2 + p], enr[ni][p]);
                    if (d < wmax) {
                        bv[wpos] = d;
                        bj4[wpos] = jb + wc * 64 + ni * 8 + tid4 * 2 + p;
                        wmax = bv[0]; wpos = 0;
                        #pragma unroll
                        for (int s = 1; s < 4; ++s)
                            if (bv[s] > wmax) { wmax = bv[s]; wpos = s; }
                    }
                }
            #pragma unroll
            for (int off = 1; off <= 2; off <<= 1) {
                #pragma unroll
                for (int s = 0; s < 4; ++s) {
                    float od = __shfl_xor_sync(0xffffffffu, bv[s], off);
                    int   oj = __shfl_xor_sync(0xffffffffu, bj4[s], off);
                    if (od < wmax) {
                        bv[wpos] = od; bj4[wpos] = oj;
                        wmax = bv[0]; wpos = 0;
                        #pragma unroll
                        for (int q = 1; q < 4; ++q)
                            if (bv[q] > wmax) { wmax = bv[q]; wpos = q; }
                    }
                }
            }
            if (tid4 == 0) {
                #pragma unroll
                for (int s = 0; s < 4; ++s) {
                    md[row * 16 + wc * 4 + s] = bv[s];
                    mj[row * 16 + wc * 4 + s] = bj4[s];
                }
            }
        }
    }
    __syncthreads();
    if (t < 128) {
        float bv[4]; int bj4[4];
        #pragma unroll
        for (int s = 0; s < 4; ++s) { bv[s] = md[t * 16 + s]; bj4[s] = mj[t * 16 + s]; }
        float wmax = bv[0]; int wpos = 0;
        #pragma unroll
        for (int s = 1; s < 4; ++s) if (bv[s] > wmax) { wmax = bv[s]; wpos = s; }
        #pragma unroll
        for (int u = 4; u < 16; ++u) {
            float od = md[t * 16 + u]; int oj = mj[t * 16 + u];
            if (od < wmax) {
                bv[wpos] = od; bj4[wpos] = oj;
                wmax = bv[0]; wpos = 0;
                #pragma unroll
                for (int q = 1; q < 4; ++q)
                    if (bv[q] > wmax) { wmax = bv[q]; wpos = q; }
            }
        }
        size_t base = (size_t)(rb + t) * 256 + (size_t)blockIdx.y * 4;
        #pragma unroll
        for (int s = 0; s < 4; ++s) { cd[base + s] = bv[s]; cj[base + s] = bj4[s]; }
    }
}

// ---------------------------------------------------------------------------
// candidate merge + exact fp32 rescore (launch 5; R2-identical semantics)
// ---------------------------------------------------------------------------
__global__ void __launch_bounds__(256)
k_cand(const float* __restrict__ cd, const int* __restrict__ cj,
       const float* __restrict__ zf, const float* __restrict__ emb,
       const float* __restrict__ en, const float* __restrict__ rn,
       int* __restrict__ idxo, float* __restrict__ fout) {
    __shared__ int lst[8][256];
    __shared__ int cnt[8];
    int w = threadIdx.x >> 5, lane = threadIdx.x & 31;
    int row = blockIdx.x * 8 + w;
    if (lane == 0) cnt[w] = 0;
    __syncwarp();

    float dv[8]; int jv[8];
    size_t base = (size_t)row * 256 + lane * 8;
    #pragma unroll
    for (int s = 0; s < 8; ++s) { dv[s] = cd[base + s]; jv[s] = cj[base + s]; }
    float mn = dv[0];
    #pragma unroll
    for (int s = 1; s < 8; ++s) mn = fminf(mn, dv[s]);
    #pragma unroll
    for (int o = 16; o > 0; o >>= 1)
        mn = fminf(mn, __shfl_xor_sync(0xffffffffu, mn, o));
    float thr = mn + CAND_MARGIN;
    #pragma unroll
    for (int s = 0; s < 8; ++s) {
        if (dv[s] <= thr) {
            int pos = atomicAdd(&cnt[w], 1);
            lst[w][pos] = jv[s];
        }
    }
    __syncwarp();
    int m = cnt[w];

    float bd = 3.4e38f; int bj = 0x7fffffff;
    const float2* z2 = reinterpret_cast<const float2*>(zf + (size_t)row * EDIM);
    float rnv = rn[row];
    for (int cc = lane; cc < m; cc += 32) {
        int j = lst[w][cc];
        const float2* e2 = reinterpret_cast<const float2*>(emb + (size_t)j * EDIM);
        float lo = 0.0f, hi = 0.0f;
        #pragma unroll 8
        for (int q = 0; q < 128; ++q) {
            float2 zz = z2[q], ee = e2[q];
            lo = __fmaf_rn(zz.x, ee.x, lo);
            hi = __fmaf_rn(zz.y, ee.y, hi);
        }
        float dot = __fadd_rn(lo, hi);
        float t1  = __fadd_rn(rnv, en[j]);
        float d   = __fsub_rn(t1, __fmul_rn(2.0f, dot));
        if (d < bd || (d == bd && j < bj)) { bd = d; bj = j; }
    }
    #pragma unroll
    for (int o = 16; o > 0; o >>= 1) {
        float od = __shfl_xor_sync(0xffffffffu, bd, o);
        int   oj = __shfl_xor_sync(0xffffffffu, bj, o);
        if (od < bd || (od == bd && oj < bj)) { bd = od; bj = oj; }
    }
    if (lane == 0) {
        idxo[row] = bj;
        fout[OUT_ELEMS + 1 + row] = (float)bj;
    }
}

// ---------------------------------------------------------------------------
__global__ void k_loss(const float* __restrict__ zf, const float* __restrict__ emb,
                       const int* __restrict__ idx, float* __restrict__ part) {
    int t = threadIdx.x;
    size_t base = (size_t)blockIdx.x * 32768;
    float acc = 0.0f;
    for (int i = 0; i < 128; ++i) {
        size_t e = base + t + (size_t)i * 256;
        int n = (int)(e >> 8);
        float d = emb[(size_t)idx[n] * EDIM + t] - zf[e];
        acc += d * d;
    }
    __shared__ float sm[256];
    sm[t] = acc;
    __syncthreads();
    #pragma unroll
    for (int o = 128; o > 0; o >>= 1) {
        if (t < o) sm[t] += sm[t + o];
        __syncthreads();
    }
    if (t == 0) part[blockIdx.x] = sm[0];
}

__global__ void k_fin(const float* __restrict__ part, float* __restrict__ out) {
    if (threadIdx.x == 0 && blockIdx.x == 0) {
        float s = 0.0f;
        for (int i = 0; i < 64; ++i) s += part[i];
        out[OUT_ELEMS] = 1.25f * s / 2097152.0f;
    }
}

__global__ void k_unpatch(const float* __restrict__ outp, float* __restrict__ out) {
    int gid = blockIdx.x * 256 + threadIdx.x;
    int ww = gid & 63, hh = (gid >> 6) & 63;
    int ch = (gid >> 12) & 255, bi = gid >> 20;
    int n = bi * 1024 + (hh >> 1) * 32 + (ww >> 1);
    int kin = ch * 4 + (hh & 1) * 2 + (ww & 1);
    out[gid] = outp[(size_t)n * PIN + kin];
}

// ---------------------------------------------------------------------------
extern "C" void kernel_launch(void* const* d_in, const int* in_sizes, int n_in,
                              void* d_out, int out_size) {
    const float* z     = (const float*)d_in[0];
    const float* emb   = (const float*)d_in[1];
    const float* W_pe  = (const float*)d_in[2];
    const float* b_pe  = (const float*)d_in[3];
    const float* gamma = (const float*)d_in[4];
    const float* beta  = (const float*)d_in[5];
    const float* W_pu  = (const float*)d_in[6];
    const float* b_pu  = (const float*)d_in[7];
    float* out = (float*)d_out;

    float *patches, *x, *zf, *rn, *wpet, *wput, *en, *outp, *cdp, *lpart;
    __nv_bfloat16 *zbf, *ebf;
    int *cjp, *idx;
    cudaGetSymbolAddress((void**)&patches, g_patches);
    cudaGetSymbolAddress((void**)&x,       g_x);
    cudaGetSymbolAddress((void**)&zf,      g_zf);
    cudaGetSymbolAddress((void**)&rn,      g_rn);
    cudaGetSymbolAddress((void**)&wpet,    g_wpet);
    cudaGetSymbolAddress((void**)&wput,    g_wput);
    cudaGetSymbolAddress((void**)&en,      g_en);
    cudaGetSymbolAddress((void**)&outp,    g_outp);
    cudaGetSymbolAddress((void**)&zbf,     g_zbf);
    cudaGetSymbolAddress((void**)&ebf,     g_ebf);
    cudaGetSymbolAddress((void**)&cdp,     g_cd);
    cudaGetSymbolAddress((void**)&cjp,     g_cj);
    cudaGetSymbolAddress((void**)&idx,     g_idx);
    cudaGetSymbolAddress((void**)&lpart,   g_losspart);

    cudaFuncSetAttribute(k_mma_dist, cudaFuncAttributeMaxDynamicSharedMemorySize,
                         DSMEM);

    // launch 1: fused prep
    k_pre1<<<51200, 256>>>(z, W_pe, W_pu, emb, patches, wpet, wput, ebf, en);
    // launch 2: x = patches @ W_pe + b_pe
    k_gemm<false><<<dim3(64, 2), 256>>>(patches, wpet, b_pe, x, nullptr,
                                        PIN, EDIM, PIN / 16);
    // launch 3: LayerNorm (+ rn, zbf)
    k_ln<<<NROWS / 8, 256>>>(x, gamma, beta, zf, rn, zbf);
    // launch 4: tensor-core distance (profiled slot)
    k_mma_dist<<<dim3(64, 64), 512, DSMEM>>>(zbf, ebf, en, cdp, cjp);
    // launch 5: candidates + exact rescore
    k_cand<<<1024, 256>>>(cdp, cjp, zf, emb, en, rn, idx, out);
    // launch 6: outp = emb[idx] @ W_pu + b_pu
    k_gemm<true><<<dim3(64, 8), 256>>>(emb, wput, b_pu, outp, idx,
                                       EDIM, PIN, EDIM / 16);
    k_loss<<<64, 256>>>(zf, emb, idx, lpart);
    k_fin<<<1, 32>>>(lpart, out);
    k_unpatch<<<32768, 256>>>(outp, out);
    (void)in_sizes; (void)n_in; (void)out_size;
}